// round 15
// baseline (speedup 1.0000x reference)
#include <cuda_runtime.h>
#include <cuda_fp16.h>
#include <cstdint>

#define N_NODES 50000
#define N_EDGES 800000
#define IN_CH   128
#define H_CH    128
#define NCAT    256

// ---------------- device scratch ----------------
__device__ __half d_gh[N_NODES * NCAT];        // fp16 row n: [g_l(128) | g_r(128)]
__device__ int    d_count[N_NODES];            // invariant: zero at entry (scanC re-zeroes)
__device__ int    d_start[N_NODES + 1];
__device__ int    d_cursor[N_NODES];
__device__ int2   d_edge_sorted[N_EDGES];      // {src, env_bits} -> {src, ex_bits} after score
__device__ int    d_dst_sorted[N_EDGES];       // dst per sorted edge (score kernel only)
__device__ int    d_bsum[128];

// ---------------- helpers ----------------
__device__ __forceinline__ unsigned long long pack2(float lo, float hi) {
    unsigned long long r;
    asm("mov.b64 %0, {%1, %2};" : "=l"(r) : "f"(lo), "f"(hi));
    return r;
}
__device__ __forceinline__ void unpack2(unsigned long long v, float& lo, float& hi) {
    asm("mov.b64 {%0, %1}, %2;" : "=f"(lo), "=f"(hi) : "l"(v));
}
__device__ __forceinline__ unsigned long long fma2(unsigned long long a,
                                                   unsigned long long b,
                                                   unsigned long long c) {
    unsigned long long d;
    asm("fma.rn.f32x2 %0, %1, %2, %3;" : "=l"(d) : "l"(a), "l"(b), "l"(c));
    return d;
}
__device__ __forceinline__ __half2 tanh2_approx(__half2 x) {
    __half2 y;
    asm("tanh.approx.f16x2 %0, %1;" : "=r"(*(unsigned*)&y) : "r"(*(unsigned*)&x));
    return y;
}

// ---------------- SGEMM via FFMA2 -> fp16 table ----------------
#define BM 64
#define BN 64
#define BK 16
#define PAD 68

__global__ __launch_bounds__(256) void gemm_kernel(const float* __restrict__ q,
                                                   const float* __restrict__ Wl,
                                                   const float* __restrict__ Wr) {
    __shared__ float As[BK][PAD];
    __shared__ float Bs[BK][PAD];

    const int block_m = blockIdx.x * BM;
    const int block_n = blockIdx.y * BN;
    const int tid = threadIdx.x;
    const int tn = tid & 15;
    const int tm = tid >> 4;

    const int lrow  = tid >> 2;
    const int lcol4 = (tid & 3) << 2;

    const int brow = block_n + lrow;
    const float* wrow = (brow < H_CH) ? (Wl + brow * IN_CH)
                                      : (Wr + (brow - H_CH) * IN_CH);

    unsigned long long acc2[4][2];
#pragma unroll
    for (int i = 0; i < 4; i++) { acc2[i][0] = 0ULL; acc2[i][1] = 0ULL; }

#pragma unroll
    for (int k0 = 0; k0 < IN_CH; k0 += BK) {
        float4 av = make_float4(0.f, 0.f, 0.f, 0.f);
        int arow = block_m + lrow;
        if (arow < N_NODES)
            av = *reinterpret_cast<const float4*>(&q[arow * IN_CH + k0 + lcol4]);
        As[lcol4 + 0][lrow] = av.x;
        As[lcol4 + 1][lrow] = av.y;
        As[lcol4 + 2][lrow] = av.z;
        As[lcol4 + 3][lrow] = av.w;
        float4 bv = *reinterpret_cast<const float4*>(&wrow[k0 + lcol4]);
        Bs[lcol4 + 0][lrow] = bv.x;
        Bs[lcol4 + 1][lrow] = bv.y;
        Bs[lcol4 + 2][lrow] = bv.z;
        Bs[lcol4 + 3][lrow] = bv.w;
        __syncthreads();

#pragma unroll
        for (int kk = 0; kk < BK; kk++) {
            float4 a = *reinterpret_cast<const float4*>(&As[kk][tm << 2]);
            float4 b = *reinterpret_cast<const float4*>(&Bs[kk][tn << 2]);
            unsigned long long bp0 = pack2(b.x, b.y);
            unsigned long long bp1 = pack2(b.z, b.w);
            float ar[4] = {a.x, a.y, a.z, a.w};
#pragma unroll
            for (int i = 0; i < 4; i++) {
                unsigned long long ad = pack2(ar[i], ar[i]);
                acc2[i][0] = fma2(ad, bp0, acc2[i][0]);
                acc2[i][1] = fma2(ad, bp1, acc2[i][1]);
            }
        }
        __syncthreads();
    }

#pragma unroll
    for (int i = 0; i < 4; i++) {
        int row = block_m + (tm << 2) + i;
        if (row < N_NODES) {
            float o0, o1, o2, o3;
            unpack2(acc2[i][0], o0, o1);
            unpack2(acc2[i][1], o2, o3);
            __half2 h01 = __floats2half2_rn(o0, o1);
            __half2 h23 = __floats2half2_rn(o2, o3);
            uint2 packed = make_uint2(*(unsigned*)&h01, *(unsigned*)&h23);
            *reinterpret_cast<uint2*>(&d_gh[row * NCAT + block_n + (tn << 2)]) = packed;
        }
    }
}

// ---------------- histogram of dst (8 edges/thread) ----------------
__global__ void hist_kernel(const int* __restrict__ ei) {
    int t = blockIdx.x * blockDim.x + threadIdx.x;
    int i8 = t * 8;
    if (i8 < N_EDGES) {
        int4 d0 = *reinterpret_cast<const int4*>(&ei[N_EDGES + i8]);
        int4 d1 = *reinterpret_cast<const int4*>(&ei[N_EDGES + i8 + 4]);
        atomicAdd(&d_count[d0.x], 1);
        atomicAdd(&d_count[d0.y], 1);
        atomicAdd(&d_count[d0.z], 1);
        atomicAdd(&d_count[d0.w], 1);
        atomicAdd(&d_count[d1.x], 1);
        atomicAdd(&d_count[d1.y], 1);
        atomicAdd(&d_count[d1.z], 1);
        atomicAdd(&d_count[d1.w], 1);
    }
}

// ---------------- scan phase A ----------------
#define SCANA_T 512
#define SCAN_NBLK ((N_NODES + SCANA_T - 1) / SCANA_T)   // 98

__global__ __launch_bounds__(SCANA_T) void scanA_kernel() {
    __shared__ int wt[16];
    int tid = threadIdx.x;
    int lane = tid & 31;
    int wid = tid >> 5;
    int idx = blockIdx.x * SCANA_T + tid;

    int v = (idx < N_NODES) ? d_count[idx] : 0;
    int ws = v;
#pragma unroll
    for (int off = 1; off < 32; off <<= 1) {
        int y = __shfl_up_sync(0xffffffffu, ws, off);
        if (lane >= off) ws += y;
    }
    if (lane == 31) wt[wid] = ws;
    __syncthreads();
    if (tid < 16) {
        int y = wt[tid];
#pragma unroll
        for (int off = 1; off < 16; off <<= 1) {
            int z = __shfl_up_sync(0x0000ffffu, y, off);
            if (tid >= off) y += z;
        }
        wt[tid] = y;
    }
    __syncthreads();
    int incl = ws + (wid ? wt[wid - 1] : 0);
    if (idx < N_NODES) d_start[idx] = incl - v;
    if (tid == SCANA_T - 1) d_bsum[blockIdx.x] = incl;
}

// ---------------- scan phase C ----------------
__global__ __launch_bounds__(SCANA_T) void scanC_kernel() {
    __shared__ int off_s;
    int tid = threadIdx.x;
    int bx = blockIdx.x;
    if (tid < 32) {
        int partial = 0;
        for (int i = tid; i < bx; i += 32) partial += d_bsum[i];
#pragma unroll
        for (int off = 16; off > 0; off >>= 1)
            partial += __shfl_xor_sync(0xffffffffu, partial, off);
        if (tid == 0) off_s = partial;
    }
    __syncthreads();
    int idx = bx * SCANA_T + tid;
    if (idx < N_NODES) {
        int e = d_start[idx] + off_s;
        d_start[idx]  = e;
        d_cursor[idx] = e;
        d_count[idx]  = 0;
    }
    if (bx == 0 && tid == 0) d_start[N_NODES] = N_EDGES;
}

// ---------------- scatter edges (8/thread) ----------------
__global__ void scatter_kernel(const int* __restrict__ ei,
                               const float* __restrict__ envelope) {
    int t = blockIdx.x * blockDim.x + threadIdx.x;
    int i8 = t * 8;
    if (i8 < N_EDGES) {
        int4   s0 = *reinterpret_cast<const int4*>(&ei[i8]);
        int4   s1 = *reinterpret_cast<const int4*>(&ei[i8 + 4]);
        int4   d0 = *reinterpret_cast<const int4*>(&ei[N_EDGES + i8]);
        int4   d1 = *reinterpret_cast<const int4*>(&ei[N_EDGES + i8 + 4]);
        float4 e0 = *reinterpret_cast<const float4*>(&envelope[i8]);
        float4 e1 = *reinterpret_cast<const float4*>(&envelope[i8 + 4]);

        int p;
        p = atomicAdd(&d_cursor[d0.x], 1);
        if ((unsigned)p < N_EDGES) { d_edge_sorted[p] = make_int2(s0.x, __float_as_int(e0.x)); d_dst_sorted[p] = d0.x; }
        p = atomicAdd(&d_cursor[d0.y], 1);
        if ((unsigned)p < N_EDGES) { d_edge_sorted[p] = make_int2(s0.y, __float_as_int(e0.y)); d_dst_sorted[p] = d0.y; }
        p = atomicAdd(&d_cursor[d0.z], 1);
        if ((unsigned)p < N_EDGES) { d_edge_sorted[p] = make_int2(s0.z, __float_as_int(e0.z)); d_dst_sorted[p] = d0.z; }
        p = atomicAdd(&d_cursor[d0.w], 1);
        if ((unsigned)p < N_EDGES) { d_edge_sorted[p] = make_int2(s0.w, __float_as_int(e0.w)); d_dst_sorted[p] = d0.w; }
        p = atomicAdd(&d_cursor[d1.x], 1);
        if ((unsigned)p < N_EDGES) { d_edge_sorted[p] = make_int2(s1.x, __float_as_int(e1.x)); d_dst_sorted[p] = d1.x; }
        p = atomicAdd(&d_cursor[d1.y], 1);
        if ((unsigned)p < N_EDGES) { d_edge_sorted[p] = make_int2(s1.y, __float_as_int(e1.y)); d_dst_sorted[p] = d1.y; }
        p = atomicAdd(&d_cursor[d1.z], 1);
        if ((unsigned)p < N_EDGES) { d_edge_sorted[p] = make_int2(s1.z, __float_as_int(e1.z)); d_dst_sorted[p] = d1.z; }
        p = atomicAdd(&d_cursor[d1.w], 1);
        if ((unsigned)p < N_EDGES) { d_edge_sorted[p] = make_int2(s1.w, __float_as_int(e1.w)); d_dst_sorted[p] = d1.w; }
    }
}

// ---------------- score kernel: warp = 4 edges x 8 lanes, half2 silu, 3-round reduce -------
// N_EDGES % 4 == 0, so no tail handling needed.
__global__ __launch_bounds__(256) void score_kernel(const float* __restrict__ attn_w) {
    int warp_id = (blockIdx.x * blockDim.x + threadIdx.x) >> 5;
    int e0 = warp_id << 2;
    if (e0 >= N_EDGES) return;
    int lane = threadIdx.x & 31;
    int sub = lane >> 3;          // edge within group: 0..3
    int cg  = lane & 7;           // channel-group: 0..7 (16 channels each)

    int e = e0 + sub;
    int2 rec = d_edge_sorted[e];
    int src = rec.x;
    float env = __int_as_float(rec.y);
    int dst = d_dst_sorted[e];

    const uint4* glp = reinterpret_cast<const uint4*>(&d_gh[src * NCAT]);        // 16 x uint4
    const uint4* grp = reinterpret_cast<const uint4*>(&d_gh[dst * NCAT + H_CH]); // 16 x uint4

    const __half2 h05 = __float2half2_rn(0.5f);
    float p = 0.f;

#pragma unroll
    for (int it = 0; it < 2; it++) {
        int cidx = cg + (it << 3);          // uint4 index 0..15 (8 channels each)
        uint4 a = glp[cidx];
        uint4 b = grp[cidx];
        const float4 aw0 = __ldg(reinterpret_cast<const float4*>(&attn_w[cidx << 3]));
        const float4 aw1 = __ldg(reinterpret_cast<const float4*>(&attn_w[(cidx << 3) + 4]));

        unsigned ua[4] = {a.x, a.y, a.z, a.w};
        unsigned ub[4] = {b.x, b.y, b.z, b.w};
        float awf[8] = {aw0.x, aw0.y, aw0.z, aw0.w, aw1.x, aw1.y, aw1.z, aw1.w};
#pragma unroll
        for (int h = 0; h < 4; h++) {
            __half2 t  = __hadd2(*(__half2*)&ua[h], *(__half2*)&ub[h]);
            __half2 th = tanh2_approx(__hmul2(t, h05));
            __half2 sg = __hfma2(th, h05, h05);
            __half2 s  = __hmul2(t, sg);
            float2 sf = __half22float2(s);
            p = fmaf(sf.x, awf[2 * h], p);
            p = fmaf(sf.y, awf[2 * h + 1], p);
        }
    }

    // reduce over the 8-lane channel group (offsets stay within the group)
    p += __shfl_xor_sync(0xffffffffu, p, 1);
    p += __shfl_xor_sync(0xffffffffu, p, 2);
    p += __shfl_xor_sync(0xffffffffu, p, 4);

    float ex = __expf(p) * (env + 1e-7f);
    if (cg == 0) d_edge_sorted[e].y = __float_as_int(ex);
}

// ---------------- aggregate kernel: warp/node, 4ch/lane, pure gather+FMA ----------------
__device__ __forceinline__ float4 gather4h(int src, int lane) {
    uint2 raw = *reinterpret_cast<const uint2*>(&d_gh[src * NCAT + (lane << 2)]);
    float2 f0 = __half22float2(*reinterpret_cast<__half2*>(&raw.x));
    float2 f1 = __half22float2(*reinterpret_cast<__half2*>(&raw.y));
    return make_float4(f0.x, f0.y, f1.x, f1.y);
}

__global__ __launch_bounds__(256) void agg_kernel(float* __restrict__ out) {
    int warp_id = (blockIdx.x * blockDim.x + threadIdx.x) >> 5;
    if (warp_id >= N_NODES) return;
    int lane = threadIdx.x & 31;
    int n = warp_id;

    float acc0 = 0.f, acc1 = 0.f, acc2 = 0.f, acc3 = 0.f;
    float denom = 0.f;

    int js = d_start[n];
    int je = d_start[n + 1];
    js = (js < 0) ? 0 : js;
    je = (je > N_EDGES) ? N_EDGES : je;

    for (int j = js; j < je; j += 4) {
        int j1 = j + 1, j2 = j + 2, j3 = j + 3;
        bool v1 = j1 < je, v2 = j2 < je, v3 = j3 < je;
        int2 rA = d_edge_sorted[j];
        int2 rB = d_edge_sorted[v1 ? j1 : j];
        int2 rC = d_edge_sorted[v2 ? j2 : j];
        int2 rD = d_edge_sorted[v3 ? j3 : j];

        float4 gA = gather4h(rA.x, lane);
        float4 gB = gather4h(rB.x, lane);
        float4 gC = gather4h(rC.x, lane);
        float4 gD = gather4h(rD.x, lane);

        float exA = __int_as_float(rA.y);
        float exB = v1 ? __int_as_float(rB.y) : 0.f;
        float exC = v2 ? __int_as_float(rC.y) : 0.f;
        float exD = v3 ? __int_as_float(rD.y) : 0.f;

        denom += (exA + exB) + (exC + exD);
        acc0 += exA * gA.x + exB * gB.x + exC * gC.x + exD * gD.x;
        acc1 += exA * gA.y + exB * gB.y + exC * gC.y + exD * gD.y;
        acc2 += exA * gA.z + exB * gB.z + exC * gC.z + exD * gD.z;
        acc3 += exA * gA.w + exB * gB.w + exC * gC.w + exD * gD.w;
    }

    float inv = (denom > 0.f) ? (1.f / denom) : 0.f;
    float4 o = make_float4(acc0 * inv, acc1 * inv, acc2 * inv, acc3 * inv);
    *reinterpret_cast<float4*>(&out[n * H_CH + (lane << 2)]) = o;
}

// ---------------- launch ----------------
extern "C" void kernel_launch(void* const* d_in, const int* in_sizes, int n_in,
                              void* d_out, int out_size) {
    const float* q        = (const float*)d_in[0];
    const float* envelope = (const float*)d_in[3];
    const float* W_l      = (const float*)d_in[4];
    const float* W_r      = (const float*)d_in[5];
    const float* attn_w   = (const float*)d_in[6];
    const int*   ei       = (const int*)d_in[7];
    float* out = (float*)d_out;

    hist_kernel<<<(N_EDGES / 8 + 255) / 256, 256>>>(ei);
    scanA_kernel<<<SCAN_NBLK, SCANA_T>>>();
    scanC_kernel<<<SCAN_NBLK, SCANA_T>>>();

    dim3 ggrid((N_NODES + BM - 1) / BM, NCAT / BN);
    gemm_kernel<<<ggrid, 256>>>(q, W_l, W_r);        // launch #4 -> profiled

    scatter_kernel<<<(N_EDGES / 8 + 255) / 256, 256>>>(ei, envelope);

    int score_warps = N_EDGES / 4;                    // 200000 warps
    score_kernel<<<(score_warps * 32 + 255) / 256, 256>>>(attn_w);

    int agg_threads = N_NODES * 32;
    agg_kernel<<<(agg_threads + 255) / 256, 256>>>(out);
}

// round 16
// speedup vs baseline: 1.5516x; 1.5516x over previous
#include <cuda_runtime.h>
#include <cuda_fp16.h>
#include <cstdint>

#define N_NODES 50000
#define N_EDGES 800000
#define IN_CH   128
#define H_CH    128
#define NCAT    256

// ---------------- device scratch ----------------
__device__ __half d_gh[N_NODES * NCAT];        // fp16 row n: [g_l(128) | g_r(128)]
__device__ __half d_qh[N_NODES * IN_CH];       // fp16 q
__device__ __half d_wh[NCAT * IN_CH];          // fp16 [W_l; W_r]
__device__ int    d_count[N_NODES];            // invariant: zero at entry (scanC re-zeroes)
__device__ int    d_start[N_NODES + 1];
__device__ int    d_cursor[N_NODES];
__device__ int2   d_edge_sorted[N_EDGES];      // {src, env_bits}
__device__ int    d_bsum[128];

// ---------------- helpers ----------------
__device__ __forceinline__ unsigned smem_u32(const void* p) {
    return (unsigned)__cvta_generic_to_shared(p);
}
__device__ __forceinline__ void ldmat4(unsigned& r0, unsigned& r1, unsigned& r2, unsigned& r3,
                                       unsigned addr) {
    asm volatile("ldmatrix.sync.aligned.m8n8.x4.shared.b16 {%0,%1,%2,%3}, [%4];"
                 : "=r"(r0), "=r"(r1), "=r"(r2), "=r"(r3) : "r"(addr));
}
__device__ __forceinline__ void mma_16816(float& c0, float& c1, float& c2, float& c3,
                                          unsigned a0, unsigned a1, unsigned a2, unsigned a3,
                                          unsigned b0, unsigned b1) {
    asm volatile("mma.sync.aligned.m16n8k16.row.col.f32.f16.f16.f32 "
                 "{%0,%1,%2,%3}, {%4,%5,%6,%7}, {%8,%9}, {%0,%1,%2,%3};"
                 : "+f"(c0), "+f"(c1), "+f"(c2), "+f"(c3)
                 : "r"(a0), "r"(a1), "r"(a2), "r"(a3), "r"(b0), "r"(b1));
}
__device__ __forceinline__ float tanh_approx(float x) {
    float y;
    asm("tanh.approx.f32 %0, %1;" : "=f"(y) : "f"(x));
    return y;
}
__device__ __forceinline__ float silu_t(float t) {
    float th = tanh_approx(0.5f * t);
    return t * fmaf(0.5f, th, 0.5f);
}

// ---------------- convert q and W to fp16 ----------------
__global__ void convert_kernel(const float* __restrict__ q,
                               const float* __restrict__ Wl,
                               const float* __restrict__ Wr) {
    int t = blockIdx.x * blockDim.x + threadIdx.x;
    int i8 = t * 8;
    if (i8 < N_NODES * IN_CH) {
        float4 f0 = *reinterpret_cast<const float4*>(&q[i8]);
        float4 f1 = *reinterpret_cast<const float4*>(&q[i8 + 4]);
        __half2 h0 = __floats2half2_rn(f0.x, f0.y);
        __half2 h1 = __floats2half2_rn(f0.z, f0.w);
        __half2 h2 = __floats2half2_rn(f1.x, f1.y);
        __half2 h3 = __floats2half2_rn(f1.z, f1.w);
        uint4 v = make_uint4(*(unsigned*)&h0, *(unsigned*)&h1, *(unsigned*)&h2, *(unsigned*)&h3);
        *reinterpret_cast<uint4*>(&d_qh[i8]) = v;
    }
    if (i8 < NCAT * IN_CH) {
        const float* src = (i8 < H_CH * IN_CH) ? &Wl[i8] : &Wr[i8 - H_CH * IN_CH];
        float4 f0 = *reinterpret_cast<const float4*>(src);
        float4 f1 = *reinterpret_cast<const float4*>(src + 4);
        __half2 h0 = __floats2half2_rn(f0.x, f0.y);
        __half2 h1 = __floats2half2_rn(f0.z, f0.w);
        __half2 h2 = __floats2half2_rn(f1.x, f1.y);
        __half2 h3 = __floats2half2_rn(f1.z, f1.w);
        uint4 v = make_uint4(*(unsigned*)&h0, *(unsigned*)&h1, *(unsigned*)&h2, *(unsigned*)&h3);
        *reinterpret_cast<uint4*>(&d_wh[i8]) = v;
    }
}

// ---------------- tensor-core GEMM: d_gh[M,256] = qh[M,128] @ wh[256,128]^T ----------------
#define TPAD 72   // padded smem row (halves); 144 B rows -> ldmatrix conflict-free

__global__ __launch_bounds__(256) void gemm_tc(const __half* __restrict__ qh,
                                               const __half* __restrict__ wh) {
    __shared__ __half As[128][TPAD];
    __shared__ __half Bs[64][TPAD];

    const int tid = threadIdx.x;
    const int lane = tid & 31;
    const int wid = tid >> 5;
    const int wm = wid & 3;      // warp m index: rows wm*32..+32
    const int wn = wid >> 2;     // warp n index: cols wn*32..+32
    const int bm = blockIdx.x * 128;
    const int bn = blockIdx.y * 64;

    float c[2][4][4];
#pragma unroll
    for (int mi = 0; mi < 2; mi++)
#pragma unroll
        for (int ni = 0; ni < 4; ni++)
#pragma unroll
            for (int r = 0; r < 4; r++) c[mi][ni][r] = 0.f;

#pragma unroll
    for (int ko = 0; ko < IN_CH; ko += 64) {
        // load A tile: 128 rows x 64 halves = 1024 uint4
#pragma unroll
        for (int i = 0; i < 4; i++) {
            int u = i * 256 + tid;
            int row = u >> 3, seg = u & 7;
            uint4 v = make_uint4(0, 0, 0, 0);
            int grow = bm + row;
            if (grow < N_NODES)
                v = *reinterpret_cast<const uint4*>(&qh[grow * IN_CH + ko + seg * 8]);
            *reinterpret_cast<uint4*>(&As[row][seg * 8]) = v;
        }
        // load B tile: 64 rows x 64 halves = 512 uint4
#pragma unroll
        for (int i = 0; i < 2; i++) {
            int u = i * 256 + tid;
            int row = u >> 3, seg = u & 7;
            uint4 v = *reinterpret_cast<const uint4*>(&wh[(bn + row) * IN_CH + ko + seg * 8]);
            *reinterpret_cast<uint4*>(&Bs[row][seg * 8]) = v;
        }
        __syncthreads();

#pragma unroll
        for (int ks = 0; ks < 4; ks++) {
            unsigned a[2][4];
#pragma unroll
            for (int mi = 0; mi < 2; mi++) {
                unsigned addr = smem_u32(
                    &As[wm * 32 + mi * 16 + (lane & 15)][ks * 16 + ((lane >> 4) << 3)]);
                ldmat4(a[mi][0], a[mi][1], a[mi][2], a[mi][3], addr);
            }
            unsigned b[4][2];
#pragma unroll
            for (int np = 0; np < 2; np++) {
                // x4 mats: (n0-7,k0-7),(n0-7,k8-15),(n8-15,k0-7),(n8-15,k8-15)
                unsigned addr = smem_u32(
                    &Bs[wn * 32 + np * 16 + (lane & 7) + ((lane >> 4) << 3)]
                       [ks * 16 + (((lane >> 3) & 1) << 3)]);
                ldmat4(b[np * 2][0], b[np * 2][1], b[np * 2 + 1][0], b[np * 2 + 1][1], addr);
            }
#pragma unroll
            for (int mi = 0; mi < 2; mi++)
#pragma unroll
                for (int ni = 0; ni < 4; ni++)
                    mma_16816(c[mi][ni][0], c[mi][ni][1], c[mi][ni][2], c[mi][ni][3],
                              a[mi][0], a[mi][1], a[mi][2], a[mi][3],
                              b[ni][0], b[ni][1]);
        }
        __syncthreads();
    }

    // epilogue: c frag (m16n8 f32) -> fp16 table
    int g = lane >> 2, t4 = lane & 3;
#pragma unroll
    for (int mi = 0; mi < 2; mi++) {
#pragma unroll
        for (int ni = 0; ni < 4; ni++) {
            int row0 = bm + wm * 32 + mi * 16 + g;
            int col  = bn + wn * 32 + ni * 8 + t4 * 2;
            if (row0 < N_NODES) {
                __half2 h = __floats2half2_rn(c[mi][ni][0], c[mi][ni][1]);
                *reinterpret_cast<__half2*>(&d_gh[row0 * NCAT + col]) = h;
            }
            int row1 = row0 + 8;
            if (row1 < N_NODES) {
                __half2 h = __floats2half2_rn(c[mi][ni][2], c[mi][ni][3]);
                *reinterpret_cast<__half2*>(&d_gh[row1 * NCAT + col]) = h;
            }
        }
    }
}

// ---------------- histogram of dst (8 edges/thread) ----------------
__global__ void hist_kernel(const int* __restrict__ ei) {
    int t = blockIdx.x * blockDim.x + threadIdx.x;
    int i8 = t * 8;
    if (i8 < N_EDGES) {
        int4 d0 = *reinterpret_cast<const int4*>(&ei[N_EDGES + i8]);
        int4 d1 = *reinterpret_cast<const int4*>(&ei[N_EDGES + i8 + 4]);
        atomicAdd(&d_count[d0.x], 1);
        atomicAdd(&d_count[d0.y], 1);
        atomicAdd(&d_count[d0.z], 1);
        atomicAdd(&d_count[d0.w], 1);
        atomicAdd(&d_count[d1.x], 1);
        atomicAdd(&d_count[d1.y], 1);
        atomicAdd(&d_count[d1.z], 1);
        atomicAdd(&d_count[d1.w], 1);
    }
}

// ---------------- scan phase A ----------------
#define SCANA_T 512
#define SCAN_NBLK ((N_NODES + SCANA_T - 1) / SCANA_T)   // 98

__global__ __launch_bounds__(SCANA_T) void scanA_kernel() {
    __shared__ int wt[16];
    int tid = threadIdx.x;
    int lane = tid & 31;
    int wid = tid >> 5;
    int idx = blockIdx.x * SCANA_T + tid;

    int v = (idx < N_NODES) ? d_count[idx] : 0;
    int ws = v;
#pragma unroll
    for (int off = 1; off < 32; off <<= 1) {
        int y = __shfl_up_sync(0xffffffffu, ws, off);
        if (lane >= off) ws += y;
    }
    if (lane == 31) wt[wid] = ws;
    __syncthreads();
    if (tid < 16) {
        int y = wt[tid];
#pragma unroll
        for (int off = 1; off < 16; off <<= 1) {
            int z = __shfl_up_sync(0x0000ffffu, y, off);
            if (tid >= off) y += z;
        }
        wt[tid] = y;
    }
    __syncthreads();
    int incl = ws + (wid ? wt[wid - 1] : 0);
    if (idx < N_NODES) d_start[idx] = incl - v;
    if (tid == SCANA_T - 1) d_bsum[blockIdx.x] = incl;
}

// ---------------- scan phase C ----------------
__global__ __launch_bounds__(SCANA_T) void scanC_kernel() {
    __shared__ int off_s;
    int tid = threadIdx.x;
    int bx = blockIdx.x;
    if (tid < 32) {
        int partial = 0;
        for (int i = tid; i < bx; i += 32) partial += d_bsum[i];
#pragma unroll
        for (int off = 16; off > 0; off >>= 1)
            partial += __shfl_xor_sync(0xffffffffu, partial, off);
        if (tid == 0) off_s = partial;
    }
    __syncthreads();
    int idx = bx * SCANA_T + tid;
    if (idx < N_NODES) {
        int e = d_start[idx] + off_s;
        d_start[idx]  = e;
        d_cursor[idx] = e;
        d_count[idx]  = 0;
    }
    if (bx == 0 && tid == 0) d_start[N_NODES] = N_EDGES;
}

// ---------------- scatter edges (8/thread, int2 records, bounds-guarded) ----------------
__global__ void scatter_kernel(const int* __restrict__ ei,
                               const float* __restrict__ envelope) {
    int t = blockIdx.x * blockDim.x + threadIdx.x;
    int i8 = t * 8;
    if (i8 < N_EDGES) {
        int4   s0 = *reinterpret_cast<const int4*>(&ei[i8]);
        int4   s1 = *reinterpret_cast<const int4*>(&ei[i8 + 4]);
        int4   d0 = *reinterpret_cast<const int4*>(&ei[N_EDGES + i8]);
        int4   d1 = *reinterpret_cast<const int4*>(&ei[N_EDGES + i8 + 4]);
        float4 e0 = *reinterpret_cast<const float4*>(&envelope[i8]);
        float4 e1 = *reinterpret_cast<const float4*>(&envelope[i8 + 4]);

        int p;
        p = atomicAdd(&d_cursor[d0.x], 1);
        if ((unsigned)p < N_EDGES) d_edge_sorted[p] = make_int2(s0.x, __float_as_int(e0.x));
        p = atomicAdd(&d_cursor[d0.y], 1);
        if ((unsigned)p < N_EDGES) d_edge_sorted[p] = make_int2(s0.y, __float_as_int(e0.y));
        p = atomicAdd(&d_cursor[d0.z], 1);
        if ((unsigned)p < N_EDGES) d_edge_sorted[p] = make_int2(s0.z, __float_as_int(e0.z));
        p = atomicAdd(&d_cursor[d0.w], 1);
        if ((unsigned)p < N_EDGES) d_edge_sorted[p] = make_int2(s0.w, __float_as_int(e0.w));
        p = atomicAdd(&d_cursor[d1.x], 1);
        if ((unsigned)p < N_EDGES) d_edge_sorted[p] = make_int2(s1.x, __float_as_int(e1.x));
        p = atomicAdd(&d_cursor[d1.y], 1);
        if ((unsigned)p < N_EDGES) d_edge_sorted[p] = make_int2(s1.y, __float_as_int(e1.y));
        p = atomicAdd(&d_cursor[d1.z], 1);
        if ((unsigned)p < N_EDGES) d_edge_sorted[p] = make_int2(s1.z, __float_as_int(e1.z));
        p = atomicAdd(&d_cursor[d1.w], 1);
        if ((unsigned)p < N_EDGES) d_edge_sorted[p] = make_int2(s1.w, __float_as_int(e1.w));
    }
}

// ---------------- per-node softmax + aggregation (warp/node, 4-edge unroll, fp16) ----------
__device__ __forceinline__ float4 gather4h(const __half* base, int lane) {
    uint2 raw = *reinterpret_cast<const uint2*>(base + (lane << 2));
    float2 f0 = __half22float2(*reinterpret_cast<__half2*>(&raw.x));
    float2 f1 = __half22float2(*reinterpret_cast<__half2*>(&raw.y));
    return make_float4(f0.x, f0.y, f1.x, f1.y);
}

__global__ __launch_bounds__(256) void out_kernel(const float* __restrict__ attn_w,
                                                  float* __restrict__ out) {
    int warp_id = (blockIdx.x * blockDim.x + threadIdx.x) >> 5;
    if (warp_id >= N_NODES) return;
    int lane = threadIdx.x & 31;
    int n = warp_id;

    float4 gr = gather4h(&d_gh[n * NCAT + H_CH], lane);
    float4 aw = *reinterpret_cast<const float4*>(&attn_w[lane << 2]);

    float acc0 = 0.f, acc1 = 0.f, acc2 = 0.f, acc3 = 0.f;
    float denom = 0.f;

    int js = d_start[n];
    int je = d_start[n + 1];
    js = (js < 0) ? 0 : js;
    je = (je > N_EDGES) ? N_EDGES : je;

    for (int j = js; j < je; j += 4) {
        int j1 = j + 1, j2 = j + 2, j3 = j + 3;
        bool v1 = j1 < je, v2 = j2 < je, v3 = j3 < je;
        int2 rA = d_edge_sorted[j];
        int2 rB = d_edge_sorted[v1 ? j1 : j];
        int2 rC = d_edge_sorted[v2 ? j2 : j];
        int2 rD = d_edge_sorted[v3 ? j3 : j];

        float4 gA = gather4h(&d_gh[rA.x * NCAT], lane);
        float4 gB = gather4h(&d_gh[rB.x * NCAT], lane);
        float4 gC = gather4h(&d_gh[rC.x * NCAT], lane);
        float4 gD = gather4h(&d_gh[rD.x * NCAT], lane);

        float pA = silu_t(gA.x + gr.x) * aw.x + silu_t(gA.y + gr.y) * aw.y
                 + silu_t(gA.z + gr.z) * aw.z + silu_t(gA.w + gr.w) * aw.w;
        float pB = silu_t(gB.x + gr.x) * aw.x + silu_t(gB.y + gr.y) * aw.y
                 + silu_t(gB.z + gr.z) * aw.z + silu_t(gB.w + gr.w) * aw.w;
        float pC = silu_t(gC.x + gr.x) * aw.x + silu_t(gC.y + gr.y) * aw.y
                 + silu_t(gC.z + gr.z) * aw.z + silu_t(gC.w + gr.w) * aw.w;
        float pD = silu_t(gD.x + gr.x) * aw.x + silu_t(gD.y + gr.y) * aw.y
                 + silu_t(gD.z + gr.z) * aw.z + silu_t(gD.w + gr.w) * aw.w;

#pragma unroll
        for (int off = 16; off > 0; off >>= 1) {
            pA += __shfl_xor_sync(0xffffffffu, pA, off);
            pB += __shfl_xor_sync(0xffffffffu, pB, off);
            pC += __shfl_xor_sync(0xffffffffu, pC, off);
            pD += __shfl_xor_sync(0xffffffffu, pD, off);
        }

        float exA = __expf(pA) * (__int_as_float(rA.y) + 1e-7f);
        float exB = v1 ? (__expf(pB) * (__int_as_float(rB.y) + 1e-7f)) : 0.f;
        float exC = v2 ? (__expf(pC) * (__int_as_float(rC.y) + 1e-7f)) : 0.f;
        float exD = v3 ? (__expf(pD) * (__int_as_float(rD.y) + 1e-7f)) : 0.f;

        denom += (exA + exB) + (exC + exD);
        acc0 += exA * gA.x + exB * gB.x + exC * gC.x + exD * gD.x;
        acc1 += exA * gA.y + exB * gB.y + exC * gC.y + exD * gD.y;
        acc2 += exA * gA.z + exB * gB.z + exC * gC.z + exD * gD.z;
        acc3 += exA * gA.w + exB * gB.w + exC * gC.w + exD * gD.w;
    }

    float inv = (denom > 0.f) ? (1.f / denom) : 0.f;
    float4 o = make_float4(acc0 * inv, acc1 * inv, acc2 * inv, acc3 * inv);
    *reinterpret_cast<float4*>(&out[n * H_CH + (lane << 2)]) = o;
}

// ---------------- launch ----------------
extern "C" void kernel_launch(void* const* d_in, const int* in_sizes, int n_in,
                              void* d_out, int out_size) {
    const float* q        = (const float*)d_in[0];
    const float* envelope = (const float*)d_in[3];
    const float* W_l      = (const float*)d_in[4];
    const float* W_r      = (const float*)d_in[5];
    const float* attn_w   = (const float*)d_in[6];
    const int*   ei       = (const int*)d_in[7];
    float* out = (float*)d_out;

    // resolve device-symbol addresses for kernel args
    __half* qh_p = nullptr;
    __half* wh_p = nullptr;
    cudaGetSymbolAddress((void**)&qh_p, d_qh);
    cudaGetSymbolAddress((void**)&wh_p, d_wh);

    convert_kernel<<<(N_NODES * IN_CH / 8 + 255) / 256, 256>>>(q, W_l, W_r);

    dim3 ggrid((N_NODES + 127) / 128, NCAT / 64);
    gemm_tc<<<ggrid, 256>>>(qh_p, wh_p);

    hist_kernel<<<(N_EDGES / 8 + 255) / 256, 256>>>(ei);
    scanA_kernel<<<SCAN_NBLK, SCANA_T>>>();
    scanC_kernel<<<SCAN_NBLK, SCANA_T>>>();
    scatter_kernel<<<(N_EDGES / 8 + 255) / 256, 256>>>(ei, envelope);

    int total_threads = N_NODES * 32;
    out_kernel<<<(total_threads + 255) / 256, 256>>>(attn_w, out);
}

// round 17
// speedup vs baseline: 1.6451x; 1.0602x over previous
#include <cuda_runtime.h>
#include <cuda_fp16.h>
#include <cstdint>

#define N_NODES 50000
#define N_EDGES 800000
#define IN_CH   128
#define H_CH    128
#define NCAT    256

// ---------------- device scratch ----------------
__device__ __half d_gh[N_NODES * NCAT];        // fp16 row n: [g_l(128) | g_r(128)]
__device__ __half d_qh[N_NODES * IN_CH];       // fp16 q
__device__ __half d_wh[NCAT * IN_CH];          // fp16 [W_l; W_r]
__device__ int    d_count[N_NODES];            // invariant: zero at entry (scanC re-zeroes)
__device__ int    d_start[N_NODES + 1];
__device__ int    d_rank[N_EDGES];             // within-dst rank of each edge
__device__ int2   d_edge_sorted[N_EDGES];      // {src, env_bits}
__device__ int    d_bsum[128];

// ---------------- helpers ----------------
__device__ __forceinline__ unsigned smem_u32(const void* p) {
    return (unsigned)__cvta_generic_to_shared(p);
}
__device__ __forceinline__ void ldmat4(unsigned& r0, unsigned& r1, unsigned& r2, unsigned& r3,
                                       unsigned addr) {
    asm volatile("ldmatrix.sync.aligned.m8n8.x4.shared.b16 {%0,%1,%2,%3}, [%4];"
                 : "=r"(r0), "=r"(r1), "=r"(r2), "=r"(r3) : "r"(addr));
}
__device__ __forceinline__ void mma_16816(float& c0, float& c1, float& c2, float& c3,
                                          unsigned a0, unsigned a1, unsigned a2, unsigned a3,
                                          unsigned b0, unsigned b1) {
    asm volatile("mma.sync.aligned.m16n8k16.row.col.f32.f16.f16.f32 "
                 "{%0,%1,%2,%3}, {%4,%5,%6,%7}, {%8,%9}, {%0,%1,%2,%3};"
                 : "+f"(c0), "+f"(c1), "+f"(c2), "+f"(c3)
                 : "r"(a0), "r"(a1), "r"(a2), "r"(a3), "r"(b0), "r"(b1));
}
__device__ __forceinline__ __half2 tanh2_approx(__half2 x) {
    __half2 y;
    asm("tanh.approx.f16x2 %0, %1;" : "=r"(*(unsigned*)&y) : "r"(*(unsigned*)&x));
    return y;
}

// ---------------- convert q and W to fp16 ----------------
__global__ void convert_kernel(const float* __restrict__ q,
                               const float* __restrict__ Wl,
                               const float* __restrict__ Wr) {
    int t = blockIdx.x * blockDim.x + threadIdx.x;
    int i8 = t * 8;
    if (i8 < N_NODES * IN_CH) {
        float4 f0 = *reinterpret_cast<const float4*>(&q[i8]);
        float4 f1 = *reinterpret_cast<const float4*>(&q[i8 + 4]);
        __half2 h0 = __floats2half2_rn(f0.x, f0.y);
        __half2 h1 = __floats2half2_rn(f0.z, f0.w);
        __half2 h2 = __floats2half2_rn(f1.x, f1.y);
        __half2 h3 = __floats2half2_rn(f1.z, f1.w);
        uint4 v = make_uint4(*(unsigned*)&h0, *(unsigned*)&h1, *(unsigned*)&h2, *(unsigned*)&h3);
        *reinterpret_cast<uint4*>(&d_qh[i8]) = v;
    }
    if (i8 < NCAT * IN_CH) {
        const float* src = (i8 < H_CH * IN_CH) ? &Wl[i8] : &Wr[i8 - H_CH * IN_CH];
        float4 f0 = *reinterpret_cast<const float4*>(src);
        float4 f1 = *reinterpret_cast<const float4*>(src + 4);
        __half2 h0 = __floats2half2_rn(f0.x, f0.y);
        __half2 h1 = __floats2half2_rn(f0.z, f0.w);
        __half2 h2 = __floats2half2_rn(f1.x, f1.y);
        __half2 h3 = __floats2half2_rn(f1.z, f1.w);
        uint4 v = make_uint4(*(unsigned*)&h0, *(unsigned*)&h1, *(unsigned*)&h2, *(unsigned*)&h3);
        *reinterpret_cast<uint4*>(&d_wh[i8]) = v;
    }
}

// ---------------- tensor-core GEMM: d_gh[M,256] = qh[M,128] @ wh[256,128]^T ----------------
#define TPAD 72

__global__ __launch_bounds__(256) void gemm_tc(const __half* __restrict__ qh,
                                               const __half* __restrict__ wh) {
    __shared__ __half As[128][TPAD];
    __shared__ __half Bs[64][TPAD];

    const int tid = threadIdx.x;
    const int lane = tid & 31;
    const int wid = tid >> 5;
    const int wm = wid & 3;
    const int wn = wid >> 2;
    const int bm = blockIdx.x * 128;
    const int bn = blockIdx.y * 64;

    float c[2][4][4];
#pragma unroll
    for (int mi = 0; mi < 2; mi++)
#pragma unroll
        for (int ni = 0; ni < 4; ni++)
#pragma unroll
            for (int r = 0; r < 4; r++) c[mi][ni][r] = 0.f;

#pragma unroll
    for (int ko = 0; ko < IN_CH; ko += 64) {
#pragma unroll
        for (int i = 0; i < 4; i++) {
            int u = i * 256 + tid;
            int row = u >> 3, seg = u & 7;
            uint4 v = make_uint4(0, 0, 0, 0);
            int grow = bm + row;
            if (grow < N_NODES)
                v = *reinterpret_cast<const uint4*>(&qh[grow * IN_CH + ko + seg * 8]);
            *reinterpret_cast<uint4*>(&As[row][seg * 8]) = v;
        }
#pragma unroll
        for (int i = 0; i < 2; i++) {
            int u = i * 256 + tid;
            int row = u >> 3, seg = u & 7;
            uint4 v = *reinterpret_cast<const uint4*>(&wh[(bn + row) * IN_CH + ko + seg * 8]);
            *reinterpret_cast<uint4*>(&Bs[row][seg * 8]) = v;
        }
        __syncthreads();

#pragma unroll
        for (int ks = 0; ks < 4; ks++) {
            unsigned a[2][4];
#pragma unroll
            for (int mi = 0; mi < 2; mi++) {
                unsigned addr = smem_u32(
                    &As[wm * 32 + mi * 16 + (lane & 15)][ks * 16 + ((lane >> 4) << 3)]);
                ldmat4(a[mi][0], a[mi][1], a[mi][2], a[mi][3], addr);
            }
            unsigned b[4][2];
#pragma unroll
            for (int np = 0; np < 2; np++) {
                unsigned addr = smem_u32(
                    &Bs[wn * 32 + np * 16 + (lane & 7) + ((lane >> 4) << 3)]
                       [ks * 16 + (((lane >> 3) & 1) << 3)]);
                ldmat4(b[np * 2][0], b[np * 2][1], b[np * 2 + 1][0], b[np * 2 + 1][1], addr);
            }
#pragma unroll
            for (int mi = 0; mi < 2; mi++)
#pragma unroll
                for (int ni = 0; ni < 4; ni++)
                    mma_16816(c[mi][ni][0], c[mi][ni][1], c[mi][ni][2], c[mi][ni][3],
                              a[mi][0], a[mi][1], a[mi][2], a[mi][3],
                              b[ni][0], b[ni][1]);
        }
        __syncthreads();
    }

    int g = lane >> 2, t4 = lane & 3;
#pragma unroll
    for (int mi = 0; mi < 2; mi++) {
#pragma unroll
        for (int ni = 0; ni < 4; ni++) {
            int row0 = bm + wm * 32 + mi * 16 + g;
            int col  = bn + wn * 32 + ni * 8 + t4 * 2;
            if (row0 < N_NODES) {
                __half2 h = __floats2half2_rn(c[mi][ni][0], c[mi][ni][1]);
                *reinterpret_cast<__half2*>(&d_gh[row0 * NCAT + col]) = h;
            }
            int row1 = row0 + 8;
            if (row1 < N_NODES) {
                __half2 h = __floats2half2_rn(c[mi][ni][2], c[mi][ni][3]);
                *reinterpret_cast<__half2*>(&d_gh[row1 * NCAT + col]) = h;
            }
        }
    }
}

// ---------------- histogram of dst (8 edges/thread) + rank capture ----------------
__global__ void hist_kernel(const int* __restrict__ ei) {
    int t = blockIdx.x * blockDim.x + threadIdx.x;
    int i8 = t * 8;
    if (i8 < N_EDGES) {
        int4 d0 = *reinterpret_cast<const int4*>(&ei[N_EDGES + i8]);
        int4 d1 = *reinterpret_cast<const int4*>(&ei[N_EDGES + i8 + 4]);
        int4 r0, r1;
        r0.x = atomicAdd(&d_count[d0.x], 1);
        r0.y = atomicAdd(&d_count[d0.y], 1);
        r0.z = atomicAdd(&d_count[d0.z], 1);
        r0.w = atomicAdd(&d_count[d0.w], 1);
        r1.x = atomicAdd(&d_count[d1.x], 1);
        r1.y = atomicAdd(&d_count[d1.y], 1);
        r1.z = atomicAdd(&d_count[d1.z], 1);
        r1.w = atomicAdd(&d_count[d1.w], 1);
        *reinterpret_cast<int4*>(&d_rank[i8])     = r0;
        *reinterpret_cast<int4*>(&d_rank[i8 + 4]) = r1;
    }
}

// ---------------- scan phase A ----------------
#define SCANA_T 512
#define SCAN_NBLK ((N_NODES + SCANA_T - 1) / SCANA_T)   // 98

__global__ __launch_bounds__(SCANA_T) void scanA_kernel() {
    __shared__ int wt[16];
    int tid = threadIdx.x;
    int lane = tid & 31;
    int wid = tid >> 5;
    int idx = blockIdx.x * SCANA_T + tid;

    int v = (idx < N_NODES) ? d_count[idx] : 0;
    int ws = v;
#pragma unroll
    for (int off = 1; off < 32; off <<= 1) {
        int y = __shfl_up_sync(0xffffffffu, ws, off);
        if (lane >= off) ws += y;
    }
    if (lane == 31) wt[wid] = ws;
    __syncthreads();
    if (tid < 16) {
        int y = wt[tid];
#pragma unroll
        for (int off = 1; off < 16; off <<= 1) {
            int z = __shfl_up_sync(0x0000ffffu, y, off);
            if (tid >= off) y += z;
        }
        wt[tid] = y;
    }
    __syncthreads();
    int incl = ws + (wid ? wt[wid - 1] : 0);
    if (idx < N_NODES) d_start[idx] = incl - v;
    if (tid == SCANA_T - 1) d_bsum[blockIdx.x] = incl;
}

// ---------------- scan phase C ----------------
__global__ __launch_bounds__(SCANA_T) void scanC_kernel() {
    __shared__ int off_s;
    int tid = threadIdx.x;
    int bx = blockIdx.x;
    if (tid < 32) {
        int partial = 0;
        for (int i = tid; i < bx; i += 32) partial += d_bsum[i];
#pragma unroll
        for (int off = 16; off > 0; off >>= 1)
            partial += __shfl_xor_sync(0xffffffffu, partial, off);
        if (tid == 0) off_s = partial;
    }
    __syncthreads();
    int idx = bx * SCANA_T + tid;
    if (idx < N_NODES) {
        d_start[idx] = d_start[idx] + off_s;
        d_count[idx] = 0;
    }
    if (bx == 0 && tid == 0) d_start[N_NODES] = N_EDGES;
}

// ---------------- scatter edges: pos = start[dst] + rank (NO atomics) ----------------
__global__ void scatter_kernel(const int* __restrict__ ei,
                               const float* __restrict__ envelope) {
    int t = blockIdx.x * blockDim.x + threadIdx.x;
    int i8 = t * 8;
    if (i8 < N_EDGES) {
        int4   s0 = *reinterpret_cast<const int4*>(&ei[i8]);
        int4   s1 = *reinterpret_cast<const int4*>(&ei[i8 + 4]);
        int4   d0 = *reinterpret_cast<const int4*>(&ei[N_EDGES + i8]);
        int4   d1 = *reinterpret_cast<const int4*>(&ei[N_EDGES + i8 + 4]);
        int4   r0 = *reinterpret_cast<const int4*>(&d_rank[i8]);
        int4   r1 = *reinterpret_cast<const int4*>(&d_rank[i8 + 4]);
        float4 e0 = *reinterpret_cast<const float4*>(&envelope[i8]);
        float4 e1 = *reinterpret_cast<const float4*>(&envelope[i8 + 4]);

        int p;
        p = d_start[d0.x] + r0.x;
        if ((unsigned)p < N_EDGES) d_edge_sorted[p] = make_int2(s0.x, __float_as_int(e0.x));
        p = d_start[d0.y] + r0.y;
        if ((unsigned)p < N_EDGES) d_edge_sorted[p] = make_int2(s0.y, __float_as_int(e0.y));
        p = d_start[d0.z] + r0.z;
        if ((unsigned)p < N_EDGES) d_edge_sorted[p] = make_int2(s0.z, __float_as_int(e0.z));
        p = d_start[d0.w] + r0.w;
        if ((unsigned)p < N_EDGES) d_edge_sorted[p] = make_int2(s0.w, __float_as_int(e0.w));
        p = d_start[d1.x] + r1.x;
        if ((unsigned)p < N_EDGES) d_edge_sorted[p] = make_int2(s1.x, __float_as_int(e1.x));
        p = d_start[d1.y] + r1.y;
        if ((unsigned)p < N_EDGES) d_edge_sorted[p] = make_int2(s1.y, __float_as_int(e1.y));
        p = d_start[d1.z] + r1.z;
        if ((unsigned)p < N_EDGES) d_edge_sorted[p] = make_int2(s1.z, __float_as_int(e1.z));
        p = d_start[d1.w] + r1.w;
        if ((unsigned)p < N_EDGES) d_edge_sorted[p] = make_int2(s1.w, __float_as_int(e1.w));
    }
}

// ---------------- per-node softmax + aggregation (warp/node, 4-edge unroll, half2 math) ----
__global__ __launch_bounds__(256) void out_kernel(const float* __restrict__ attn_w,
                                                  float* __restrict__ out) {
    int warp_id = (blockIdx.x * blockDim.x + threadIdx.x) >> 5;
    if (warp_id >= N_NODES) return;
    int lane = threadIdx.x & 31;
    int n = warp_id;

    uint2 grr = *reinterpret_cast<const uint2*>(&d_gh[n * NCAT + H_CH + (lane << 2)]);
    __half2 gr01 = *(__half2*)&grr.x;
    __half2 gr23 = *(__half2*)&grr.y;
    float4 awf = *reinterpret_cast<const float4*>(&attn_w[lane << 2]);
    __half2 aw01 = __floats2half2_rn(awf.x, awf.y);
    __half2 aw23 = __floats2half2_rn(awf.z, awf.w);
    const __half2 h05 = __float2half2_rn(0.5f);

    float acc0 = 0.f, acc1 = 0.f, acc2 = 0.f, acc3 = 0.f;
    float denom = 0.f;

    int js = d_start[n];
    int je = d_start[n + 1];
    js = (js < 0) ? 0 : js;
    je = (je > N_EDGES) ? N_EDGES : je;

    for (int j = js; j < je; j += 4) {
        int j1 = j + 1, j2 = j + 2, j3 = j + 3;
        bool v1 = j1 < je, v2 = j2 < je, v3 = j3 < je;
        int2 rA = d_edge_sorted[j];
        int2 rB = d_edge_sorted[v1 ? j1 : j];
        int2 rC = d_edge_sorted[v2 ? j2 : j];
        int2 rD = d_edge_sorted[v3 ? j3 : j];

        uint2 hA = *reinterpret_cast<const uint2*>(&d_gh[rA.x * NCAT + (lane << 2)]);
        uint2 hB = *reinterpret_cast<const uint2*>(&d_gh[rB.x * NCAT + (lane << 2)]);
        uint2 hC = *reinterpret_cast<const uint2*>(&d_gh[rC.x * NCAT + (lane << 2)]);
        uint2 hD = *reinterpret_cast<const uint2*>(&d_gh[rD.x * NCAT + (lane << 2)]);

        // half2 silu + dot per edge
        float pA, pB, pC, pD;
        {
            __half2 t0 = __hadd2(*(__half2*)&hA.x, gr01);
            __half2 t1 = __hadd2(*(__half2*)&hA.y, gr23);
            __half2 s0 = __hmul2(t0, __hfma2(tanh2_approx(__hmul2(t0, h05)), h05, h05));
            __half2 s1 = __hmul2(t1, __hfma2(tanh2_approx(__hmul2(t1, h05)), h05, h05));
            __half2 d2 = __hfma2(s1, aw23, __hmul2(s0, aw01));
            float2 df = __half22float2(d2);
            pA = df.x + df.y;
        }
        {
            __half2 t0 = __hadd2(*(__half2*)&hB.x, gr01);
            __half2 t1 = __hadd2(*(__half2*)&hB.y, gr23);
            __half2 s0 = __hmul2(t0, __hfma2(tanh2_approx(__hmul2(t0, h05)), h05, h05));
            __half2 s1 = __hmul2(t1, __hfma2(tanh2_approx(__hmul2(t1, h05)), h05, h05));
            __half2 d2 = __hfma2(s1, aw23, __hmul2(s0, aw01));
            float2 df = __half22float2(d2);
            pB = df.x + df.y;
        }
        {
            __half2 t0 = __hadd2(*(__half2*)&hC.x, gr01);
            __half2 t1 = __hadd2(*(__half2*)&hC.y, gr23);
            __half2 s0 = __hmul2(t0, __hfma2(tanh2_approx(__hmul2(t0, h05)), h05, h05));
            __half2 s1 = __hmul2(t1, __hfma2(tanh2_approx(__hmul2(t1, h05)), h05, h05));
            __half2 d2 = __hfma2(s1, aw23, __hmul2(s0, aw01));
            float2 df = __half22float2(d2);
            pC = df.x + df.y;
        }
        {
            __half2 t0 = __hadd2(*(__half2*)&hD.x, gr01);
            __half2 t1 = __hadd2(*(__half2*)&hD.y, gr23);
            __half2 s0 = __hmul2(t0, __hfma2(tanh2_approx(__hmul2(t0, h05)), h05, h05));
            __half2 s1 = __hmul2(t1, __hfma2(tanh2_approx(__hmul2(t1, h05)), h05, h05));
            __half2 d2 = __hfma2(s1, aw23, __hmul2(s0, aw01));
            float2 df = __half22float2(d2);
            pD = df.x + df.y;
        }

#pragma unroll
        for (int off = 16; off > 0; off >>= 1) {
            pA += __shfl_xor_sync(0xffffffffu, pA, off);
            pB += __shfl_xor_sync(0xffffffffu, pB, off);
            pC += __shfl_xor_sync(0xffffffffu, pC, off);
            pD += __shfl_xor_sync(0xffffffffu, pD, off);
        }

        float exA = __expf(pA) * (__int_as_float(rA.y) + 1e-7f);
        float exB = v1 ? (__expf(pB) * (__int_as_float(rB.y) + 1e-7f)) : 0.f;
        float exC = v2 ? (__expf(pC) * (__int_as_float(rC.y) + 1e-7f)) : 0.f;
        float exD = v3 ? (__expf(pD) * (__int_as_float(rD.y) + 1e-7f)) : 0.f;

        float2 fA0 = __half22float2(*(__half2*)&hA.x);
        float2 fA1 = __half22float2(*(__half2*)&hA.y);
        float2 fB0 = __half22float2(*(__half2*)&hB.x);
        float2 fB1 = __half22float2(*(__half2*)&hB.y);
        float2 fC0 = __half22float2(*(__half2*)&hC.x);
        float2 fC1 = __half22float2(*(__half2*)&hC.y);
        float2 fD0 = __half22float2(*(__half2*)&hD.x);
        float2 fD1 = __half22float2(*(__half2*)&hD.y);

        denom += (exA + exB) + (exC + exD);
        acc0 += exA * fA0.x + exB * fB0.x + exC * fC0.x + exD * fD0.x;
        acc1 += exA * fA0.y + exB * fB0.y + exC * fC0.y + exD * fD0.y;
        acc2 += exA * fA1.x + exB * fB1.x + exC * fC1.x + exD * fD1.x;
        acc3 += exA * fA1.y + exB * fB1.y + exC * fC1.y + exD * fD1.y;
    }

    float inv = (denom > 0.f) ? (1.f / denom) : 0.f;
    float4 o = make_float4(acc0 * inv, acc1 * inv, acc2 * inv, acc3 * inv);
    *reinterpret_cast<float4*>(&out[n * H_CH + (lane << 2)]) = o;
}

// ---------------- launch ----------------
extern "C" void kernel_launch(void* const* d_in, const int* in_sizes, int n_in,
                              void* d_out, int out_size) {
    const float* q        = (const float*)d_in[0];
    const float* envelope = (const float*)d_in[3];
    const float* W_l      = (const float*)d_in[4];
    const float* W_r      = (const float*)d_in[5];
    const float* attn_w   = (const float*)d_in[6];
    const int*   ei       = (const int*)d_in[7];
    float* out = (float*)d_out;

    __half* qh_p = nullptr;
    __half* wh_p = nullptr;
    cudaGetSymbolAddress((void**)&qh_p, d_qh);
    cudaGetSymbolAddress((void**)&wh_p, d_wh);

    convert_kernel<<<(N_NODES * IN_CH / 8 + 255) / 256, 256>>>(q, W_l, W_r);

    dim3 ggrid((N_NODES + 127) / 128, NCAT / 64);
    gemm_tc<<<ggrid, 256>>>(qh_p, wh_p);

    hist_kernel<<<(N_EDGES / 8 + 255) / 256, 256>>>(ei);
    scanA_kernel<<<SCAN_NBLK, SCANA_T>>>();
    scanC_kernel<<<SCAN_NBLK, SCANA_T>>>();
    scatter_kernel<<<(N_EDGES / 8 + 255) / 256, 256>>>(ei, envelope);

    int total_threads = N_NODES * 32;
    out_kernel<<<(total_threads + 255) / 256, 256>>>(attn_w, out);
}